// round 8
// baseline (speedup 1.0000x reference)
#include <cuda_runtime.h>
#include <cstdint>

#define D 128
#define MT 16              // rows per tile (500000 = 31250 * 16)
#define LDX 132            // smem row stride (floats); 132%32=4 -> conflict-free ldmatrix
#define NTHREADS 128       // 4 warps; warp w owns output cols [32w, 32w+32)
#define GRID 304           // 2 CTAs/SM * 152 SMs (persistent)
#define STAGES 6
#define STAGE_FLOATS (MT * LDX)             // 2112
#define STAGE_BYTES  (STAGE_FLOATS * 4)     // 8448
#define PAIR_BYTES   (2 * STAGE_BYTES)      // x tile + mask tile per stage (16896)

// Scratch for W' = W @ S, pre-rounded to tf32 (allocation-free per harness rules)
__device__ __align__(16) float g_wprime[D * D];

__device__ __forceinline__ float tf32_rna(float v) {
    uint32_t r;
    asm("cvt.rna.tf32.f32 %0, %1;" : "=r"(r) : "f"(v));
    return __uint_as_float(r);
}
__device__ __forceinline__ uint32_t smem_u32(const void* p) {
    return (uint32_t)__cvta_generic_to_shared(p);
}
__device__ __forceinline__ void mbar_wait(uint32_t mb, uint32_t parity) {
    asm volatile(
        "{\n\t"
        ".reg .pred P;\n\t"
        "WAIT_%=: mbarrier.try_wait.parity.acquire.cta.shared::cta.b64 P, [%0], %1, 0x989680;\n\t"
        "@P bra.uni DONE_%=;\n\t"
        "bra.uni WAIT_%=;\n\t"
        "DONE_%=:\n\t"
        "}"
        :: "r"(mb), "r"(parity) : "memory");
}

// ---------------------------------------------------------------------------
// Kernel 1: W' = W @ S in exact fp32, then round once to tf32. Trivial cost.
// ---------------------------------------------------------------------------
__global__ void wprime_kernel(const float* __restrict__ W, const float* __restrict__ S) {
    __shared__ float wrow[D];
    const int i = blockIdx.x;
    const int j = threadIdx.x;
    wrow[j] = W[i * D + j];
    __syncthreads();
    float acc = 0.f;
#pragma unroll
    for (int k = 0; k < D; ++k) acc = fmaf(wrow[k], S[k * D + j], acc);
    g_wprime[i * D + j] = tf32_rna(acc);
}

// ---------------------------------------------------------------------------
// Kernel 2: out = relu((x .* mask) @ W')
// 6-stage TMA-bulk pipeline (warp 0 produces, 33 instr/tile vs 2048 LDGSTS).
// Dropout multiply on ldmatrix fragments; W' register-resident per warp.
// ---------------------------------------------------------------------------
__global__ __launch_bounds__(NTHREADS, 2) void gcn_kernel(
    const float* __restrict__ x, const float* __restrict__ mask,
    float* __restrict__ out, int nrows, int ntiles)
{
    extern __shared__ float smem[];          // STAGES * PAIR_BYTES
    __shared__ __align__(8) uint64_t mbar[STAGES];
    const uint32_t sbase = smem_u32(smem);

    const int tid  = threadIdx.x;
    const int wid  = tid >> 5;
    const int lane = tid & 31;
    const int g    = lane >> 2;  // 0..7
    const int tg   = lane & 3;   // 0..3

    if (tid == 0) {
#pragma unroll
        for (int s = 0; s < STAGES; ++s)
            asm volatile("mbarrier.init.shared.b64 [%0], 1;"
                         :: "r"(smem_u32(&mbar[s])) : "memory");
    }

    // ---- Preload B fragments (K=128 x N=32 per warp) into registers, once ----
    // tf32 m16n8k8 B (col-major 8x8 block): b0 = B[tg][n], b1 = B[tg+4][n]
    uint32_t breg[16][4][2];
#pragma unroll
    for (int kb = 0; kb < 16; ++kb)
#pragma unroll
        for (int nb = 0; nb < 4; ++nb) {
            const int col = wid * 32 + nb * 8 + g;
            breg[kb][nb][0] = __float_as_uint(g_wprime[(kb * 8 + tg    ) * D + col]);
            breg[kb][nb][1] = __float_as_uint(g_wprime[(kb * 8 + tg + 4) * D + col]);
        }

    // ---- ldmatrix per-lane offset ----
    const int lrow  = (lane & 7) + ((lane >> 3) & 1) * 8;
    const int lcoff = (lane >> 4) * 4;
    const uint32_t laneoff = (uint32_t)((lrow * LDX + lcoff) * 4);

    __syncthreads();   // mbarrier init visible

    // ---- Producer: warp 0 only. 1 expect_tx + 32 bulk copies (512B/row) ----
    auto issue_stage = [&](int tile, int s) {
        if (tile >= ntiles) return;
        const int valid = min(MT, nrows - tile * MT);
        const uint32_t mb = smem_u32(&mbar[s]);
        if (lane == 0)
            asm volatile("mbarrier.arrive.expect_tx.shared.b64 _, [%0], %1;"
                         :: "r"(mb), "r"(valid * 2 * D * 4) : "memory");
        const int row = lane >> 1;
        if (row < valid) {
            const float* src = (lane & 1)
                ? (mask + ((size_t)tile * MT + row) * D)
                : (x    + ((size_t)tile * MT + row) * D);
            const uint32_t dst = sbase + (uint32_t)s * PAIR_BYTES
                               + (uint32_t)(lane & 1) * STAGE_BYTES
                               + (uint32_t)(row * LDX * 4);
            asm volatile("cp.async.bulk.shared::cta.global.mbarrier::complete_tx::bytes "
                         "[%0], [%1], %2, [%3];"
                         :: "r"(dst), "l"(src), "r"(D * 4), "r"(mb) : "memory");
        }
    };

    // ---- Prologue: STAGES-1 stages in flight ----
    if (wid == 0) {
#pragma unroll
        for (int s = 0; s < STAGES - 1; ++s)
            issue_stage(blockIdx.x + s * GRID, s);
    }

    int p = 0, ph = 0;
    for (int t = blockIdx.x; t < ntiles; t += GRID) {
        mbar_wait(smem_u32(&mbar[p]), (uint32_t)ph);
        __syncthreads();   // all warps past previous compute -> stage (p-1) reusable

        if (wid == 0)
            issue_stage(t + (STAGES - 1) * GRID, (p + STAGES - 1) % STAGES);

        // ---- Compute tile t from stage p ----
        const uint32_t ax = sbase + (uint32_t)p * PAIR_BYTES + laneoff;
        const uint32_t am = ax + STAGE_BYTES;
        float acc[4][4] = {{0.f,0.f,0.f,0.f},{0.f,0.f,0.f,0.f},
                           {0.f,0.f,0.f,0.f},{0.f,0.f,0.f,0.f}};
#pragma unroll
        for (int kb = 0; kb < 16; ++kb) {
            uint32_t x0, x1, x2, x3, m0, m1, m2, m3;
            asm volatile("ldmatrix.sync.aligned.m8n8.x4.shared.b16 {%0,%1,%2,%3}, [%4];"
                         : "=r"(x0), "=r"(x1), "=r"(x2), "=r"(x3) : "r"(ax + kb * 32));
            asm volatile("ldmatrix.sync.aligned.m8n8.x4.shared.b16 {%0,%1,%2,%3}, [%4];"
                         : "=r"(m0), "=r"(m1), "=r"(m2), "=r"(m3) : "r"(am + kb * 32));
            const uint32_t a0 = __float_as_uint(tf32_rna(__uint_as_float(x0) * __uint_as_float(m0)));
            const uint32_t a1 = __float_as_uint(tf32_rna(__uint_as_float(x1) * __uint_as_float(m1)));
            const uint32_t a2 = __float_as_uint(tf32_rna(__uint_as_float(x2) * __uint_as_float(m2)));
            const uint32_t a3 = __float_as_uint(tf32_rna(__uint_as_float(x3) * __uint_as_float(m3)));
#pragma unroll
            for (int nb = 0; nb < 4; ++nb) {
                asm volatile(
                    "mma.sync.aligned.m16n8k8.row.col.f32.tf32.tf32.f32 "
                    "{%0,%1,%2,%3}, {%4,%5,%6,%7}, {%8,%9}, {%0,%1,%2,%3};"
                    : "+f"(acc[nb][0]), "+f"(acc[nb][1]), "+f"(acc[nb][2]), "+f"(acc[nb][3])
                    : "r"(a0), "r"(a1), "r"(a2), "r"(a3),
                      "r"(breg[kb][nb][0]), "r"(breg[kb][nb][1]));
            }
        }

        // ---- Epilogue: ReLU + STG.64 (C: rows g/g+8, cols 2tg,2tg+1) ----
        const int r0 = t * MT + g;
        const int r1 = r0 + 8;
#pragma unroll
        for (int nb = 0; nb < 4; ++nb) {
            const int c = wid * 32 + nb * 8 + 2 * tg;
            if (r0 < nrows) {
                float2 v; v.x = fmaxf(acc[nb][0], 0.f); v.y = fmaxf(acc[nb][1], 0.f);
                *reinterpret_cast<float2*>(out + (size_t)r0 * D + c) = v;
            }
            if (r1 < nrows) {
                float2 v; v.x = fmaxf(acc[nb][2], 0.f); v.y = fmaxf(acc[nb][3], 0.f);
                *reinterpret_cast<float2*>(out + (size_t)r1 * D + c) = v;
            }
        }

        if (++p == STAGES) { p = 0; ph ^= 1; }
    }
}

// ---------------------------------------------------------------------------
// Harness entry
// ---------------------------------------------------------------------------
extern "C" void kernel_launch(void* const* d_in, const int* in_sizes, int n_in,
                              void* d_out, int out_size) {
    const float* x    = (const float*)d_in[0];   // [N, 128]
    const float* W    = (const float*)d_in[1];   // [128, 128]
    const float* S    = (const float*)d_in[2];   // [128, 128]
    const float* mask = (const float*)d_in[3];   // [N, 128]
    float* out = (float*)d_out;

    const int nrows  = in_sizes[0] / D;
    const int ntiles = (nrows + MT - 1) / MT;

    const size_t smem = (size_t)STAGES * PAIR_BYTES;   // ~99 KB
    cudaFuncSetAttribute(gcn_kernel, cudaFuncAttributeMaxDynamicSharedMemorySize, (int)smem);

    wprime_kernel<<<D, D>>>(W, S);
    gcn_kernel<<<GRID, NTHREADS, smem>>>(x, mask, out, nrows, ntiles);
}

// round 9
// speedup vs baseline: 1.2336x; 1.2336x over previous
#include <cuda_runtime.h>
#include <cstdint>

#define D 128
#define MT 32              // rows per tile (500000 = 15625 * 32, exact)
#define LDX 132            // smem row stride (floats); 132%32=4 -> conflict-free ldmatrix
#define NTHREADS 128       // 4 warps; warp w owns output cols [32w, 32w+32)
#define GRID 304           // 2 CTAs/SM * 152 SMs (persistent)
#define STAGES 3
#define STAGE_FLOATS (MT * LDX)             // 4224
#define STAGE_BYTES  (STAGE_FLOATS * 4)     // 16896
#define PAIR_BYTES   (2 * STAGE_BYTES)      // x tile + mask tile per stage (33792)

// Scratch for W' = W @ S, pre-rounded to tf32 (allocation-free per harness rules)
__device__ __align__(16) float g_wprime[D * D];

__device__ __forceinline__ float tf32_rna(float v) {
    uint32_t r;
    asm("cvt.rna.tf32.f32 %0, %1;" : "=r"(r) : "f"(v));
    return __uint_as_float(r);
}
__device__ __forceinline__ uint32_t smem_u32(const void* p) {
    return (uint32_t)__cvta_generic_to_shared(p);
}

// ---------------------------------------------------------------------------
// Kernel 1: W' = W @ S in exact fp32, then round once to tf32. Trivial cost.
// ---------------------------------------------------------------------------
__global__ void wprime_kernel(const float* __restrict__ W, const float* __restrict__ S) {
    __shared__ float wrow[D];
    const int i = blockIdx.x;
    const int j = threadIdx.x;
    wrow[j] = W[i * D + j];
    __syncthreads();
    float acc = 0.f;
#pragma unroll
    for (int k = 0; k < D; ++k) acc = fmaf(wrow[k], S[k * D + j], acc);
    g_wprime[i * D + j] = tf32_rna(acc);
}

// ---------------------------------------------------------------------------
// Kernel 2: out = relu((x .* mask) @ W')
// 3-stage cp.async pipeline, MT=32: each warp computes TWO independent 16-row
// M-blocks per tile (8 accumulator tiles) -> 2x in-warp ILP to cover the
// ldmatrix->cvt->mma chains at low occupancy. W' register-resident per warp.
// ---------------------------------------------------------------------------
__global__ __launch_bounds__(NTHREADS, 2) void gcn_kernel(
    const float* __restrict__ x, const float* __restrict__ mask,
    float* __restrict__ out, int nrows, int ntiles)
{
    extern __shared__ float smem[];   // STAGES * 2 * STAGE_FLOATS
    const uint32_t sbase = smem_u32(smem);

    const int tid  = threadIdx.x;
    const int wid  = tid >> 5;
    const int lane = tid & 31;
    const int g    = lane >> 2;  // 0..7
    const int tg   = lane & 3;   // 0..3

    // ---- Preload B fragments (K=128 x N=32 per warp) into registers, once ----
    // tf32 m16n8k8 B (col-major 8x8 block): b0 = B[tg][n], b1 = B[tg+4][n]
    uint32_t breg[16][4][2];
#pragma unroll
    for (int kb = 0; kb < 16; ++kb)
#pragma unroll
        for (int nb = 0; nb < 4; ++nb) {
            const int col = wid * 32 + nb * 8 + g;
            breg[kb][nb][0] = __float_as_uint(g_wprime[(kb * 8 + tg    ) * D + col]);
            breg[kb][nb][1] = __float_as_uint(g_wprime[(kb * 8 + tg + 4) * D + col]);
        }

    // ---- ldmatrix per-lane offset (within a 16-row block) ----
    const int lrow  = (lane & 7) + ((lane >> 3) & 1) * 8;
    const int lcoff = (lane >> 4) * 4;
    const uint32_t laneoff = (uint32_t)((lrow * LDX + lcoff) * 4);

    // ---- cp.async: each thread copies 8 x 16B per array per tile ----
    auto issue_stage = [&](int tile, int s) {
        const uint32_t xdst = sbase + (uint32_t)s * PAIR_BYTES;
        const uint32_t mdst = xdst + STAGE_BYTES;
#pragma unroll
        for (int i = 0; i < 8; ++i) {
            const int e   = tid + i * NTHREADS;      // 0..1023 = 32 rows x 32 chunks
            const int row = e >> 5, c4 = e & 31;
            int r = tile * MT + row;
            const int sz = (tile < ntiles && r < nrows) ? 16 : 0;  // zero-fill OOB
            if (r >= nrows) r = 0;
            const uint32_t doff = (uint32_t)((row * LDX + c4 * 4) * 4);
            const float* gx = x    + (size_t)r * D + c4 * 4;
            const float* gm = mask + (size_t)r * D + c4 * 4;
            asm volatile("cp.async.cg.shared.global [%0], [%1], 16, %2;"
                         :: "r"(xdst + doff), "l"(gx), "r"(sz));
            asm volatile("cp.async.cg.shared.global [%0], [%1], 16, %2;"
                         :: "r"(mdst + doff), "l"(gm), "r"(sz));
        }
        asm volatile("cp.async.commit_group;");
    };

    // ---- Prologue: 2 stages in flight ----
#pragma unroll
    for (int s = 0; s < STAGES - 1; ++s)
        issue_stage(blockIdx.x + s * GRID, s);

    int p = 0;
    for (int t = blockIdx.x; t < ntiles; t += GRID) {
        asm volatile("cp.async.wait_group %0;" :: "n"(STAGES - 2));
        __syncthreads();   // stage p visible; prev compute done -> slot reusable

        // Refill the slot consumed last iteration
        issue_stage(t + (STAGES - 1) * GRID, (p + STAGES - 1) % STAGES);

        // ---- Compute tile t from stage p: two 16-row blocks ----
        const uint32_t ax0 = sbase + (uint32_t)p * PAIR_BYTES + laneoff;
        const uint32_t am0 = ax0 + STAGE_BYTES;
        const uint32_t blk = (uint32_t)(16 * LDX * 4);

        float acc[2][4][4];
#pragma unroll
        for (int rb = 0; rb < 2; ++rb)
#pragma unroll
            for (int nb = 0; nb < 4; ++nb)
#pragma unroll
                for (int e = 0; e < 4; ++e) acc[rb][nb][e] = 0.f;

#pragma unroll
        for (int kb = 0; kb < 16; ++kb) {
            uint32_t a[2][4];
#pragma unroll
            for (int rb = 0; rb < 2; ++rb) {
                uint32_t x0, x1, x2, x3, m0, m1, m2, m3;
                asm volatile("ldmatrix.sync.aligned.m8n8.x4.shared.b16 {%0,%1,%2,%3}, [%4];"
                             : "=r"(x0), "=r"(x1), "=r"(x2), "=r"(x3)
                             : "r"(ax0 + rb * blk + kb * 32));
                asm volatile("ldmatrix.sync.aligned.m8n8.x4.shared.b16 {%0,%1,%2,%3}, [%4];"
                             : "=r"(m0), "=r"(m1), "=r"(m2), "=r"(m3)
                             : "r"(am0 + rb * blk + kb * 32));
                a[rb][0] = __float_as_uint(tf32_rna(__uint_as_float(x0) * __uint_as_float(m0)));
                a[rb][1] = __float_as_uint(tf32_rna(__uint_as_float(x1) * __uint_as_float(m1)));
                a[rb][2] = __float_as_uint(tf32_rna(__uint_as_float(x2) * __uint_as_float(m2)));
                a[rb][3] = __float_as_uint(tf32_rna(__uint_as_float(x3) * __uint_as_float(m3)));
            }
#pragma unroll
            for (int rb = 0; rb < 2; ++rb)
#pragma unroll
                for (int nb = 0; nb < 4; ++nb) {
                    asm volatile(
                        "mma.sync.aligned.m16n8k8.row.col.f32.tf32.tf32.f32 "
                        "{%0,%1,%2,%3}, {%4,%5,%6,%7}, {%8,%9}, {%0,%1,%2,%3};"
                        : "+f"(acc[rb][nb][0]), "+f"(acc[rb][nb][1]),
                          "+f"(acc[rb][nb][2]), "+f"(acc[rb][nb][3])
                        : "r"(a[rb][0]), "r"(a[rb][1]), "r"(a[rb][2]), "r"(a[rb][3]),
                          "r"(breg[kb][nb][0]), "r"(breg[kb][nb][1]));
                }
        }

        // ---- Epilogue: ReLU + STG.64 (C: rows g/g+8, cols 2tg,2tg+1) ----
#pragma unroll
        for (int rb = 0; rb < 2; ++rb) {
            const int r0 = t * MT + rb * 16 + g;
            const int r1 = r0 + 8;
#pragma unroll
            for (int nb = 0; nb < 4; ++nb) {
                const int c = wid * 32 + nb * 8 + 2 * tg;
                if (r0 < nrows) {
                    float2 v; v.x = fmaxf(acc[rb][nb][0], 0.f); v.y = fmaxf(acc[rb][nb][1], 0.f);
                    *reinterpret_cast<float2*>(out + (size_t)r0 * D + c) = v;
                }
                if (r1 < nrows) {
                    float2 v; v.x = fmaxf(acc[rb][nb][2], 0.f); v.y = fmaxf(acc[rb][nb][3], 0.f);
                    *reinterpret_cast<float2*>(out + (size_t)r1 * D + c) = v;
                }
            }
        }
        p = (p + 1) % STAGES;
    }
}

// ---------------------------------------------------------------------------
// Harness entry
// ---------------------------------------------------------------------------
extern "C" void kernel_launch(void* const* d_in, const int* in_sizes, int n_in,
                              void* d_out, int out_size) {
    const float* x    = (const float*)d_in[0];   // [N, 128]
    const float* W    = (const float*)d_in[1];   // [128, 128]
    const float* S    = (const float*)d_in[2];   // [128, 128]
    const float* mask = (const float*)d_in[3];   // [N, 128]
    float* out = (float*)d_out;

    const int nrows  = in_sizes[0] / D;
    const int ntiles = (nrows + MT - 1) / MT;

    const size_t smem = (size_t)STAGES * PAIR_BYTES;   // ~99 KB
    cudaFuncSetAttribute(gcn_kernel, cudaFuncAttributeMaxDynamicSharedMemorySize, (int)smem);

    wprime_kernel<<<D, D>>>(W, S);
    gcn_kernel<<<GRID, NTHREADS, smem>>>(x, mask, out, nrows, ntiles);
}